// round 16
// baseline (speedup 1.0000x reference)
#include <cuda_runtime.h>
#include <cstdint>

#define THREADS  256
#define TILE     4096                 // per-tile elements (256 thr x 16)
#define KTILES   2
#define BSPAN    (TILE * KTILES)      // 8192
#define HALO     1024
#define NWARPS   (THREADS / 32)       // 8
#define FULLMASK 0xFFFFFFFFu
#define DISC     0.99f
#define PW4      0.96059601f          // 0.99^4

// y[t] = a[t]*y[t+1] + r[t],  a = terminal[t] ? 0 : DISC,  y[n] = 0.
// Halo truncation: 0.99^1024 = 3.4e-5 on the cut carry -> ~2e-6 RMS rel.
// Block = 2 tiles processed right-to-left with EXACT carry via tile-total affine.
// ALL global loads (both tiles + halo) are issued in registers up front, so the
// DRAM stream stays saturated through both tiles' compute/store phases.
__global__ void __launch_bounds__(THREADS, 5)
scan_k(const float* __restrict__ reward,
       const int*  __restrict__ term,      // bool materialized as int32 (exactly 0/1)
       float*      __restrict__ out, int n)
{
    __shared__ float s_wA[NWARPS], s_wB[NWARPS];   // owned warp aggregates
    __shared__ float s_hA[NWARPS], s_hB[NWARPS];   // halo warp aggregates
    __shared__ float s_cA[NWARPS], s_cB[NWARPS];   // per-warp exclusive carries
    __shared__ float s_tA, s_tB;                   // tile total affine
    __shared__ float s_yin;

    const int t    = threadIdx.x;
    const int lane = t & 31;
    const int wid  = t >> 5;

    const int bs   = (int)blockIdx.x * BSPAN;
    const bool fast = (bs + BSPAN + HALO <= n);
    const int fb   = (bs >> 2) + wid * 128 + lane;   // tile k, round r: fb+k*1024+r*32

    // ---------------- front-batched loads: tile1, tile0, halo --------------------
    float4   v[KTILES][4];
    unsigned tm[KTILES] = {0u, 0u}, om[KTILES] = {0u, 0u};
    float    hr[4]; unsigned hm = 0u, ho = 0u;

    if (fast) {
        const float4* rp = (const float4*)reward;
        const int4*   tp = (const int4*)term;
        #pragma unroll
        for (int k = 0; k < KTILES; ++k) {
            float4 a0 = rp[fb + k*1024 +  0], a1 = rp[fb + k*1024 + 32],
                   a2 = rp[fb + k*1024 + 64], a3 = rp[fb + k*1024 + 96];
            int4   w0 = tp[fb + k*1024 +  0], w1 = tp[fb + k*1024 + 32],
                   w2 = tp[fb + k*1024 + 64], w3 = tp[fb + k*1024 + 96];
            v[k][0]=a0; v[k][1]=a1; v[k][2]=a2; v[k][3]=a3;
            unsigned n0 = (unsigned)(w0.x + 2*w0.y + 4*w0.z + 8*w0.w);
            unsigned n1 = (unsigned)(w1.x + 2*w1.y + 4*w1.z + 8*w1.w);
            unsigned n2 = (unsigned)(w2.x + 2*w2.y + 4*w2.z + 8*w2.w);
            unsigned n3 = (unsigned)(w3.x + 2*w3.y + 4*w3.z + 8*w3.w);
            tm[k] = n0 | (n1 << 4) | (n2 << 8) | (n3 << 12);
        }
        float4 hv = rp[((bs + BSPAN) >> 2) + t];
        int4   hw = tp[((bs + BSPAN) >> 2) + t];
        hr[0]=hv.x; hr[1]=hv.y; hr[2]=hv.z; hr[3]=hv.w;
        hm = (unsigned)(hw.x + 2*hw.y + 4*hw.z + 8*hw.w);
    } else {
        #pragma unroll
        for (int k = 0; k < KTILES; ++k) {
            const int e0 = bs + k * TILE + wid * 512 + lane * 4;
            #pragma unroll
            for (int r = 0; r < 4; ++r) {
                float rv[4];
                #pragma unroll
                for (int j = 0; j < 4; ++j) {
                    int e = e0 + r * 128 + j;
                    if (e < n) {
                        rv[j] = reward[e];
                        if (term[e] != 0) tm[k] |= (1u << (4*r + j));
                    } else { rv[j] = 0.0f; om[k] |= (1u << (4*r + j)); }
                }
                v[k][r] = make_float4(rv[0], rv[1], rv[2], rv[3]);
            }
        }
        const int hs = bs + BSPAN + t * 4;
        #pragma unroll
        for (int i = 0; i < 4; ++i) {
            int g = hs + i;
            if (g < n) {
                hr[i] = reward[g];
                if (term[g] != 0) hm |= (1u << i);
            } else { hr[i] = 0.0f; ho |= (1u << i); }
        }
    }

    // ---------------- halo per-thread affine + warp suffix-compose ----------------
    {
        float hA = 1.0f, hB;
        float y = 0.0f;
        #pragma unroll
        for (int i = 3; i >= 0; --i) {
            float a = ((hm >> i) & 1u) ? 0.0f : (((ho >> i) & 1u) ? 1.0f : DISC);
            y = fmaf(a, y, hr[i]);
            hA *= a;
        }
        hB = y;
        #pragma unroll
        for (int d = 1; d < 32; d <<= 1) {
            float a2 = __shfl_down_sync(FULLMASK, hA, d);
            float b2 = __shfl_down_sync(FULLMASK, hB, d);
            if (lane + d < 32) { hB = fmaf(hA, b2, hB); hA = hA * a2; }
        }
        if (lane == 0) { s_hA[wid] = hA; s_hB[wid] = hB; }
        // no sync needed here: tile-1's cross-warp phase syncs before warp0 reads s_h*
    }

    float yin = 0.0f;   // set from s_yin after tile-1's cross-warp phase

    // ---------------- tiles, right-to-left ----------------
    #pragma unroll
    for (int ti = KTILES - 1; ti >= 0; --ti) {
        const int ts = bs + ti * TILE;
        const bool tf = (ts + TILE <= n);

        // per-segment affines
        float segA[4], segB[4];
        if (tf) {
            #pragma unroll
            for (int r = 0; r < 4; ++r) {
                unsigned m = tm[ti] >> (4 * r);
                float y = v[ti][r].w;
                y = fmaf((m & 4u) ? 0.0f : DISC, y, v[ti][r].z);
                y = fmaf((m & 2u) ? 0.0f : DISC, y, v[ti][r].y);
                y = fmaf((m & 1u) ? 0.0f : DISC, y, v[ti][r].x);
                segB[r] = y;
                segA[r] = (m & 0xFu) ? 0.0f : PW4;
            }
        } else {
            #pragma unroll
            for (int r = 0; r < 4; ++r) {
                float rv[4] = { v[ti][r].x, v[ti][r].y, v[ti][r].z, v[ti][r].w };
                float y = 0.0f, A = 1.0f;
                #pragma unroll
                for (int j = 3; j >= 0; --j) {
                    unsigned b = 4*r + j;
                    float a = ((tm[ti] >> b) & 1u) ? 0.0f
                            : (((om[ti] >> b) & 1u) ? 1.0f : DISC);
                    y = fmaf(a, y, rv[j]);
                    A *= a;
                }
                segB[r] = y; segA[r] = A;
            }
        }

        // per-round warp suffix scans; build fused exclusive affines gx[r] and
        // warp aggregate S = T0∘T1∘T2∘T3 (composition toward the left edge)
        float gxA[4], gxB[4];
        float SA = 1.0f, SB = 0.0f;
        #pragma unroll
        for (int r = 3; r >= 0; --r) {
            float Ai = segA[r], Bi = segB[r];
            #pragma unroll
            for (int d = 1; d < 32; d <<= 1) {
                float a2 = __shfl_down_sync(FULLMASK, Ai, d);
                float b2 = __shfl_down_sync(FULLMASK, Bi, d);
                if (lane + d < 32) { Bi = fmaf(Ai, b2, Bi); Ai = Ai * a2; }
            }
            float eA = __shfl_down_sync(FULLMASK, Ai, 1);   // exclusive within round
            float eB = __shfl_down_sync(FULLMASK, Bi, 1);
            if (lane == 31) { eA = 1.0f; eB = 0.0f; }
            float TAr = __shfl_sync(FULLMASK, Ai, 0);       // round total
            float TBr = __shfl_sync(FULLMASK, Bi, 0);
            gxA[r] = eA * SA;                               // ex ∘ S (S = rounds right)
            gxB[r] = fmaf(eA, SB, eB);
            SB = fmaf(TAr, SB, TBr);                        // S = T_r ∘ S
            SA = TAr * SA;
        }

        if (lane == 0) { s_wA[wid] = SA; s_wB[wid] = SB; }
        __syncthreads();

        if (wid == 0) {
            bool v8 = lane < NWARPS;
            float wa = v8 ? s_wA[lane] : 1.0f;
            float wb = v8 ? s_wB[lane] : 0.0f;
            float ha = (ti == KTILES - 1) ? (v8 ? s_hA[lane] : 1.0f) : 1.0f;
            float hb = (ti == KTILES - 1) ? (v8 ? s_hB[lane] : 0.0f) : 0.0f;
            #pragma unroll
            for (int d = 1; d < 32; d <<= 1) {
                float a2 = __shfl_down_sync(FULLMASK, wa, d);
                float b2 = __shfl_down_sync(FULLMASK, wb, d);
                float a3 = __shfl_down_sync(FULLMASK, ha, d);
                float b3 = __shfl_down_sync(FULLMASK, hb, d);
                if (lane + d < 32) {
                    wb = fmaf(wa, b2, wb); wa *= a2;
                    hb = fmaf(ha, b3, hb); ha *= a3;
                }
            }
            float ecA = __shfl_down_sync(FULLMASK, wa, 1);
            float ecB = __shfl_down_sync(FULLMASK, wb, 1);
            if (v8) {
                if (lane == NWARPS - 1) { ecA = 1.0f; ecB = 0.0f; }
                s_cA[lane] = ecA; s_cB[lane] = ecB;
            }
            if (lane == 0) {
                s_tA = wa; s_tB = wb;                      // tile total
                if (ti == KTILES - 1) s_yin = hb;          // halo applied to 0
            }
        }
        __syncthreads();

        if (ti == KTILES - 1) yin = s_yin;
        const float Yw = fmaf(s_cA[wid], yin, s_cB[wid]);  // value entering this warp

        if (tf) {
            float4* op = (float4*)out;
            #pragma unroll
            for (int r = 3; r >= 0; --r) {                 // rounds independent
                float c = fmaf(gxA[r], Yw, gxB[r]);        // carry entering segment
                unsigned m = tm[ti] >> (4 * r);
                float y = c, o0, o1, o2, o3;
                y = fmaf((m & 8u) ? 0.0f : DISC, y, v[ti][r].w); o3 = y;
                y = fmaf((m & 4u) ? 0.0f : DISC, y, v[ti][r].z); o2 = y;
                y = fmaf((m & 2u) ? 0.0f : DISC, y, v[ti][r].y); o1 = y;
                y = fmaf((m & 1u) ? 0.0f : DISC, y, v[ti][r].x); o0 = y;
                __stcs(op + fb + ti * 1024 + r * 32, make_float4(o0, o1, o2, o3));
            }
        } else {
            const int e0 = ts + wid * 512 + lane * 4;
            #pragma unroll
            for (int r = 3; r >= 0; --r) {
                float y = fmaf(gxA[r], Yw, gxB[r]);
                float rv[4] = { v[ti][r].x, v[ti][r].y, v[ti][r].z, v[ti][r].w };
                #pragma unroll
                for (int j = 3; j >= 0; --j) {
                    unsigned b = 4*r + j;
                    float a = ((tm[ti] >> b) & 1u) ? 0.0f
                            : (((om[ti] >> b) & 1u) ? 1.0f : DISC);
                    y = fmaf(a, y, rv[j]);
                    int e = e0 + r * 128 + j;
                    if (e < n) out[e] = y;
                }
            }
        }

        // exact carry into the next (left) tile
        yin = fmaf(s_tA, yin, s_tB);
    }
}

extern "C" void kernel_launch(void* const* d_in, const int* in_sizes, int n_in,
                              void* d_out, int out_size)
{
    const int*   term   = (const int*)d_in[0];     // 'terminal' (bool -> int32, 0/1)
    const float* reward = (const float*)d_in[1];   // 'reward' (f32)
    float*       out    = (float*)d_out;
    int n  = in_sizes[1];
    int nb = (n + BSPAN - 1) / BSPAN;              // 2048 for T=16777216
    scan_k<<<nb, THREADS>>>(reward, term, out, n);
}

// round 17
// speedup vs baseline: 1.1836x; 1.1836x over previous
#include <cuda_runtime.h>
#include <cstdint>

#define THREADS  256
#define TILE     4096                 // per-tile elements (256 thr x 16)
#define KTILES   2
#define BSPAN    (TILE * KTILES)      // 8192
#define HALO     1024
#define NWARPS   (THREADS / 32)       // 8
#define FULLMASK 0xFFFFFFFFu
#define DISC     0.99f
#define PW4      0.96059601f          // 0.99^4

// y[t] = a[t]*y[t+1] + r[t],  a = terminal[t] ? 0 : DISC,  y[n] = 0.
// Halo truncation: 0.99^1024 = 3.4e-5 on the cut carry -> ~2e-6 RMS rel.
// Block = 2 tiles processed right-to-left with EXACT carry via tile-total affine.
// ALL global loads (both tiles + halo) are issued in registers up front, so the
// DRAM stream stays saturated through both tiles' compute/store phases.
// NOTE: 4 blocks/SM (64 regs) is load-bearing — a 5-block/56-reg cap spills the
// register-resident tile payload (measured +10us in R16).
__global__ void __launch_bounds__(THREADS, 4)
scan_k(const float* __restrict__ reward,
       const int*  __restrict__ term,      // bool materialized as int32 (exactly 0/1)
       float*      __restrict__ out, int n)
{
    __shared__ float s_wA[NWARPS], s_wB[NWARPS];   // owned warp aggregates
    __shared__ float s_hA[NWARPS], s_hB[NWARPS];   // halo warp aggregates
    __shared__ float s_cA[NWARPS], s_cB[NWARPS];   // per-warp exclusive carries
    __shared__ float s_tA, s_tB;                   // tile total affine
    __shared__ float s_yin;

    const int t    = threadIdx.x;
    const int lane = t & 31;
    const int wid  = t >> 5;

    const int bs   = (int)blockIdx.x * BSPAN;
    const bool fast = (bs + BSPAN + HALO <= n);
    const int fb   = (bs >> 2) + wid * 128 + lane;   // tile k, round r: fb+k*1024+r*32

    // ---------------- front-batched loads: tile1, tile0, halo --------------------
    float4   v[KTILES][4];
    unsigned tm[KTILES] = {0u, 0u}, om[KTILES] = {0u, 0u};
    float    hr[4]; unsigned hm = 0u, ho = 0u;

    if (fast) {
        const float4* rp = (const float4*)reward;
        const int4*   tp = (const int4*)term;
        #pragma unroll
        for (int k = 0; k < KTILES; ++k) {
            float4 a0 = rp[fb + k*1024 +  0], a1 = rp[fb + k*1024 + 32],
                   a2 = rp[fb + k*1024 + 64], a3 = rp[fb + k*1024 + 96];
            int4   w0 = tp[fb + k*1024 +  0], w1 = tp[fb + k*1024 + 32],
                   w2 = tp[fb + k*1024 + 64], w3 = tp[fb + k*1024 + 96];
            v[k][0]=a0; v[k][1]=a1; v[k][2]=a2; v[k][3]=a3;
            unsigned n0 = (unsigned)(w0.x + 2*w0.y + 4*w0.z + 8*w0.w);
            unsigned n1 = (unsigned)(w1.x + 2*w1.y + 4*w1.z + 8*w1.w);
            unsigned n2 = (unsigned)(w2.x + 2*w2.y + 4*w2.z + 8*w2.w);
            unsigned n3 = (unsigned)(w3.x + 2*w3.y + 4*w3.z + 8*w3.w);
            tm[k] = n0 | (n1 << 4) | (n2 << 8) | (n3 << 12);
        }
        float4 hv = rp[((bs + BSPAN) >> 2) + t];
        int4   hw = tp[((bs + BSPAN) >> 2) + t];
        hr[0]=hv.x; hr[1]=hv.y; hr[2]=hv.z; hr[3]=hv.w;
        hm = (unsigned)(hw.x + 2*hw.y + 4*hw.z + 8*hw.w);
    } else {
        #pragma unroll
        for (int k = 0; k < KTILES; ++k) {
            const int e0 = bs + k * TILE + wid * 512 + lane * 4;
            #pragma unroll
            for (int r = 0; r < 4; ++r) {
                float rv[4];
                #pragma unroll
                for (int j = 0; j < 4; ++j) {
                    int e = e0 + r * 128 + j;
                    if (e < n) {
                        rv[j] = reward[e];
                        if (term[e] != 0) tm[k] |= (1u << (4*r + j));
                    } else { rv[j] = 0.0f; om[k] |= (1u << (4*r + j)); }
                }
                v[k][r] = make_float4(rv[0], rv[1], rv[2], rv[3]);
            }
        }
        const int hs = bs + BSPAN + t * 4;
        #pragma unroll
        for (int i = 0; i < 4; ++i) {
            int g = hs + i;
            if (g < n) {
                hr[i] = reward[g];
                if (term[g] != 0) hm |= (1u << i);
            } else { hr[i] = 0.0f; ho |= (1u << i); }
        }
    }

    // ---------------- halo per-thread affine + warp suffix-compose ----------------
    {
        float hA = 1.0f, hB;
        float y = 0.0f;
        #pragma unroll
        for (int i = 3; i >= 0; --i) {
            float a = ((hm >> i) & 1u) ? 0.0f : (((ho >> i) & 1u) ? 1.0f : DISC);
            y = fmaf(a, y, hr[i]);
            hA *= a;
        }
        hB = y;
        #pragma unroll
        for (int d = 1; d < 32; d <<= 1) {
            float a2 = __shfl_down_sync(FULLMASK, hA, d);
            float b2 = __shfl_down_sync(FULLMASK, hB, d);
            if (lane + d < 32) { hB = fmaf(hA, b2, hB); hA = hA * a2; }
        }
        if (lane == 0) { s_hA[wid] = hA; s_hB[wid] = hB; }
        // no sync needed here: tile-1's cross-warp phase syncs before warp0 reads s_h*
    }

    float yin = 0.0f;   // set from s_yin after tile-1's cross-warp phase

    // ---------------- tiles, right-to-left ----------------
    #pragma unroll
    for (int ti = KTILES - 1; ti >= 0; --ti) {
        const int ts = bs + ti * TILE;
        const bool tf = (ts + TILE <= n);

        // per-segment affines
        float segA[4], segB[4];
        if (tf) {
            #pragma unroll
            for (int r = 0; r < 4; ++r) {
                unsigned m = tm[ti] >> (4 * r);
                float y = v[ti][r].w;
                y = fmaf((m & 4u) ? 0.0f : DISC, y, v[ti][r].z);
                y = fmaf((m & 2u) ? 0.0f : DISC, y, v[ti][r].y);
                y = fmaf((m & 1u) ? 0.0f : DISC, y, v[ti][r].x);
                segB[r] = y;
                segA[r] = (m & 0xFu) ? 0.0f : PW4;
            }
        } else {
            #pragma unroll
            for (int r = 0; r < 4; ++r) {
                float rv[4] = { v[ti][r].x, v[ti][r].y, v[ti][r].z, v[ti][r].w };
                float y = 0.0f, A = 1.0f;
                #pragma unroll
                for (int j = 3; j >= 0; --j) {
                    unsigned b = 4*r + j;
                    float a = ((tm[ti] >> b) & 1u) ? 0.0f
                            : (((om[ti] >> b) & 1u) ? 1.0f : DISC);
                    y = fmaf(a, y, rv[j]);
                    A *= a;
                }
                segB[r] = y; segA[r] = A;
            }
        }

        // per-round warp suffix scans; build fused exclusive affines gx[r] and
        // warp aggregate S = T0∘T1∘T2∘T3 (composition toward the left edge)
        float gxA[4], gxB[4];
        float SA = 1.0f, SB = 0.0f;
        #pragma unroll
        for (int r = 3; r >= 0; --r) {
            float Ai = segA[r], Bi = segB[r];
            #pragma unroll
            for (int d = 1; d < 32; d <<= 1) {
                float a2 = __shfl_down_sync(FULLMASK, Ai, d);
                float b2 = __shfl_down_sync(FULLMASK, Bi, d);
                if (lane + d < 32) { Bi = fmaf(Ai, b2, Bi); Ai = Ai * a2; }
            }
            float eA = __shfl_down_sync(FULLMASK, Ai, 1);   // exclusive within round
            float eB = __shfl_down_sync(FULLMASK, Bi, 1);
            if (lane == 31) { eA = 1.0f; eB = 0.0f; }
            float TAr = __shfl_sync(FULLMASK, Ai, 0);       // round total
            float TBr = __shfl_sync(FULLMASK, Bi, 0);
            gxA[r] = eA * SA;                               // ex ∘ S (S = rounds right)
            gxB[r] = fmaf(eA, SB, eB);
            SB = fmaf(TAr, SB, TBr);                        // S = T_r ∘ S
            SA = TAr * SA;
        }

        if (lane == 0) { s_wA[wid] = SA; s_wB[wid] = SB; }
        __syncthreads();

        if (wid == 0) {
            bool v8 = lane < NWARPS;
            float wa = v8 ? s_wA[lane] : 1.0f;
            float wb = v8 ? s_wB[lane] : 0.0f;
            float ha = (ti == KTILES - 1) ? (v8 ? s_hA[lane] : 1.0f) : 1.0f;
            float hb = (ti == KTILES - 1) ? (v8 ? s_hB[lane] : 0.0f) : 0.0f;
            #pragma unroll
            for (int d = 1; d < 32; d <<= 1) {
                float a2 = __shfl_down_sync(FULLMASK, wa, d);
                float b2 = __shfl_down_sync(FULLMASK, wb, d);
                float a3 = __shfl_down_sync(FULLMASK, ha, d);
                float b3 = __shfl_down_sync(FULLMASK, hb, d);
                if (lane + d < 32) {
                    wb = fmaf(wa, b2, wb); wa *= a2;
                    hb = fmaf(ha, b3, hb); ha *= a3;
                }
            }
            float ecA = __shfl_down_sync(FULLMASK, wa, 1);
            float ecB = __shfl_down_sync(FULLMASK, wb, 1);
            if (v8) {
                if (lane == NWARPS - 1) { ecA = 1.0f; ecB = 0.0f; }
                s_cA[lane] = ecA; s_cB[lane] = ecB;
            }
            if (lane == 0) {
                s_tA = wa; s_tB = wb;                      // tile total
                if (ti == KTILES - 1) s_yin = hb;          // halo applied to 0
            }
        }
        __syncthreads();

        if (ti == KTILES - 1) yin = s_yin;
        const float Yw = fmaf(s_cA[wid], yin, s_cB[wid]);  // value entering this warp

        if (tf) {
            float4* op = (float4*)out;
            #pragma unroll
            for (int r = 3; r >= 0; --r) {                 // rounds independent
                float c = fmaf(gxA[r], Yw, gxB[r]);        // carry entering segment
                unsigned m = tm[ti] >> (4 * r);
                float y = c, o0, o1, o2, o3;
                y = fmaf((m & 8u) ? 0.0f : DISC, y, v[ti][r].w); o3 = y;
                y = fmaf((m & 4u) ? 0.0f : DISC, y, v[ti][r].z); o2 = y;
                y = fmaf((m & 2u) ? 0.0f : DISC, y, v[ti][r].y); o1 = y;
                y = fmaf((m & 1u) ? 0.0f : DISC, y, v[ti][r].x); o0 = y;
                __stcs(op + fb + ti * 1024 + r * 32, make_float4(o0, o1, o2, o3));
            }
        } else {
            const int e0 = ts + wid * 512 + lane * 4;
            #pragma unroll
            for (int r = 3; r >= 0; --r) {
                float y = fmaf(gxA[r], Yw, gxB[r]);
                float rv[4] = { v[ti][r].x, v[ti][r].y, v[ti][r].z, v[ti][r].w };
                #pragma unroll
                for (int j = 3; j >= 0; --j) {
                    unsigned b = 4*r + j;
                    float a = ((tm[ti] >> b) & 1u) ? 0.0f
                            : (((om[ti] >> b) & 1u) ? 1.0f : DISC);
                    y = fmaf(a, y, rv[j]);
                    int e = e0 + r * 128 + j;
                    if (e < n) out[e] = y;
                }
            }
        }

        // exact carry into the next (left) tile
        yin = fmaf(s_tA, yin, s_tB);
    }
}

extern "C" void kernel_launch(void* const* d_in, const int* in_sizes, int n_in,
                              void* d_out, int out_size)
{
    const int*   term   = (const int*)d_in[0];     // 'terminal' (bool -> int32, 0/1)
    const float* reward = (const float*)d_in[1];   // 'reward' (f32)
    float*       out    = (float*)d_out;
    int n  = in_sizes[1];
    int nb = (n + BSPAN - 1) / BSPAN;              // 2048 for T=16777216
    scan_k<<<nb, THREADS>>>(reward, term, out, n);
}